// round 16
// baseline (speedup 1.0000x reference)
#include <cuda_runtime.h>

typedef unsigned long long ull;

#define TT 1024
#define BB 32
#define DD 768
#define LLn 48
#define SSTRIDE (BB * LLn)   // 1536 floats per time step
#define NWORK 192            // emis worker CTAs
#define NBLK 512             // emis blocks (64 rows = 2 t each)
#define ONES8 0x0101010101010101ULL

// Scratch (static device globals — no allocation)
__device__ float g_eem[TT * BB * LLn];   // exp(em + bias), layout [t][b][l]
__device__ float g_eemM[TT * BB * LLn];  // tags ? 0 : eem  (for partial chain)
__device__ float g_res[64];              // [0..31]=fwd, [32..63]=par
__device__ ull   g_flag8[132];           // byte flag for t at raw byte t+7
__device__ int   g_done;
__device__ int   g_bool_dt;              // 0=uint8, 1=int32, 2=float32

__device__ __forceinline__ ull pack2(float x, float y) {
    ull r; asm("mov.b64 %0, {%1,%2};" : "=l"(r) : "f"(x), "f"(y)); return r;
}
__device__ __forceinline__ void unpack2(ull v, float& x, float& y) {
    asm("mov.b64 {%0,%1}, %2;" : "=f"(x), "=f"(y) : "l"(v));
}
__device__ __forceinline__ ull fma2(ull a, ull b, ull c) {
    ull d; asm("fma.rn.f32x2 %0, %1, %2, %3;" : "=l"(d) : "l"(a), "l"(b), "l"(c)); return d;
}
__device__ __forceinline__ ull add2(ull a, ull b) {
    ull d; asm("add.rn.f32x2 %0, %1, %2;" : "=l"(d) : "l"(a), "l"(b)); return d;
}

__device__ __forceinline__ int loadBool(const void* p, int dt, long idx) {
    if (dt == 1) return ((const int*)p)[idx] != 0;
    if (dt == 0) return ((const unsigned char*)p)[idx] != 0;
    return ((const float*)p)[idx] != 0.f;
}

// ---------------------------------------------------------------------------
// Detect boolean dtype + clear flags/done for this launch (graph replays!).
// ---------------------------------------------------------------------------
__global__ void detect_kernel(const unsigned int* __restrict__ w) {
    int i = threadIdx.x;
    if (i < 132) g_flag8[i] = 0ull;
    if (i == 255) g_done = 0;
    int f = 0, u = 0;
#pragma unroll
    for (int q = 0; q < 4; q++) {
        unsigned int v = w[i + q * 256];
        if (v == 0x3F800000u) f = 1;
        else if (v & 0xFFFFFF00u) u = 1;
    }
    int anyf = __syncthreads_or(f);
    int anyu = __syncthreads_or(u);
    if (i == 0) g_bool_dt = anyf ? 2 : (anyu ? 0 : 1);
}

// ---------------------------------------------------------------------------
// Fused kernel, 128 threads/CTA, grid 256:
//   bid 0..63   : CRF scan chain (bid<32 fwd(b), else par(b)) + combine tail
//   bid 64..255 : persistent emis workers, strided blocks (t-ordered)
// ALL shared arrays are __align__(16): the worker branch uses LDS.128 on Ws,
// and the cross-branch shared-memory union must not break 16B alignment.
// ---------------------------------------------------------------------------
#define KT 32
__global__ __launch_bounds__(128) void fused_kernel(float* __restrict__ out,
                                                    const float* __restrict__ feats,
                                                    const float* __restrict__ W,
                                                    const float* __restrict__ bias,
                                                    const void* __restrict__ tags,
                                                    const int* __restrict__ lens,
                                                    const float* __restrict__ beg,
                                                    const float* __restrict__ trans,
                                                    const float* __restrict__ endv,
                                                    const void* __restrict__ bc,
                                                    const void* __restrict__ ec,
                                                    const void* __restrict__ tc) {
    volatile unsigned char* fb = (volatile unsigned char*)g_flag8;
    const int tid = threadIdx.x;

    if (blockIdx.x >= 64) {
        // ================= emis worker =================
        __shared__ __align__(16) float2 As[64 * 17];   // 64 rows x (16 f2 + pad)
        __shared__ __align__(16) float  Ws[KT * LLn];  // 32 x 48
        const int wkr = blockIdx.x - 64;
        const int r = tid >> 1;          // row within block (0..63)
        const int h = tid & 1;           // column half
        const int dt = g_bool_dt;

        for (int blk = wkr; blk < NBLK; blk += NWORK) {
            const int base_row = blk * 64;   // rows cover t=2blk, 2blk+1
            ull acc[12];
#pragma unroll
            for (int i = 0; i < 12; i++) acc[i] = 0ull;

            for (int kt = 0; kt < DD / KT; ++kt) {
                __syncthreads();
                {
                    const float2* fg = (const float2*)(feats);
#pragma unroll
                    for (int q = 0; q < 8; q++) {
                        int n = q * 128 + tid;       // 0..1023
                        int rr = n >> 4;
                        int c2 = n & 15;
                        As[rr * 17 + c2] = fg[(size_t)(base_row + rr) * (DD / 2) + kt * (KT / 2) + c2];
                    }
                }
                {
                    const float4* wg = (const float4*)(W + kt * KT * LLn);
                    float4* ws4 = (float4*)Ws;
#pragma unroll
                    for (int q = 0; q < 3; q++) ws4[tid + 128 * q] = wg[tid + 128 * q];
                }
                __syncthreads();

                const float2* arow = As + r * 17;
#pragma unroll
                for (int k2 = 0; k2 < 16; k2++) {
                    float2 a2 = arow[k2];
                    ull d0 = pack2(a2.x, a2.x);
                    ull d1 = pack2(a2.y, a2.y);
                    const ulonglong2* w0 = (const ulonglong2*)(Ws + (2 * k2) * LLn + h * 24);
                    const ulonglong2* w1 = (const ulonglong2*)(Ws + (2 * k2 + 1) * LLn + h * 24);
#pragma unroll
                    for (int j = 0; j < 6; j++) {
                        ulonglong2 wa = w0[j];
                        ulonglong2 wb = w1[j];
                        acc[2 * j]     = fma2(d0, wa.x, acc[2 * j]);
                        acc[2 * j + 1] = fma2(d0, wa.y, acc[2 * j + 1]);
                        acc[2 * j]     = fma2(d1, wb.x, acc[2 * j]);
                        acc[2 * j + 1] = fma2(d1, wb.y, acc[2 * j + 1]);
                    }
                }
            }
            // Epilogue: bias + exp; write eem and tag-masked eemM.
            const int grow = base_row + r;
            const long ebase = (long)grow * LLn + h * 24;
            float* orow  = g_eem  + ebase;
            float* orowM = g_eemM + ebase;
#pragma unroll
            for (int jp = 0; jp < 12; jp++) {
                float x, y; unpack2(acc[jp], x, y);
                float2 o;
                o.x = __expf(x + bias[h * 24 + 2 * jp]);
                o.y = __expf(y + bias[h * 24 + 2 * jp + 1]);
                ((float2*)orow)[jp] = o;
                float2 om = o;
                if (loadBool(tags, dt, ebase + 2 * jp))     om.x = 0.f;
                if (loadBool(tags, dt, ebase + 2 * jp + 1)) om.y = 0.f;
                ((float2*)orowM)[jp] = om;
            }
            __threadfence();     // each thread fences its own stores
            __syncthreads();
            if (tid == 0) {      // publish t = 2blk, 2blk+1 (raw byte = t+7)
                fb[7 + 2 * blk] = 1;
                fb[8 + 2 * blk] = 1;
            }
        }
        return;
    }

    // ================= scan chain =================
    __shared__ __align__(16) float ubuf[2][LLn];
    __shared__ __align__(16) float wpart[4];
    __shared__ int s_last;
    const int g = tid;                   // 0..127 (warp 3 = dummy)
    const int warp = g >> 5;
    const int lane = g & 31;
    const bool realg = g < 96;
    int row = g >> 1; if (row > 47) row = 47;   // clamp dummy lanes
    const int half = g & 1;
    const int bidx = blockIdx.x;
    const int b = bidx & 31;
    const bool is_par = bidx >= 32;
    const int lenm1 = lens[b] - 1;
    const int dt = g_bool_dt;
    const float* gb = (is_par ? g_eemM : g_eem) + b * LLn + row;

    ull EH[12];
#pragma unroll
    for (int j = 0; j < 12; j++) {
        int k = half * 24 + 2 * j;
        float e0 = __expf(trans[row * LLn + k]);
        float e1 = __expf(trans[row * LLn + k + 1]);
        if (is_par) {
            if (loadBool(tc, dt, row * LLn + k))     e0 = 0.f;
            if (loadBool(tc, dt, row * LLn + k + 1)) e1 = 0.f;
        }
        EH[j] = pack2(e0, e1);
    }
    float Eend = 0.f;
    if (half == 0 && realg) {
        Eend = __expf(endv[row]);
        if (is_par && loadBool(ec, dt, row)) Eend = 0.f;
    }

    // wait for t=0..8 availability (raw bytes 7..15)
    while (fb[7] == 0) {}
    {
        volatile ull* fw = (volatile ull*)g_flag8 + 1;   // bytes 8..15 = t 1..8
        while (*fw != ONES8) {}
    }
    __threadfence();

    // t = 0 init (eemM folds tags; bc applied here)
    if (half == 0 && realg) {
        float u0 = __ldg(gb) * __expf(beg[row]);
        if (is_par && loadBool(bc, dt, row)) u0 = 0.f;
        ubuf[0][row] = u0;
    }
    __syncthreads();

    float c = 0.f;
    int p = 0;
    int t = 1;
    float val = 0.f;

    auto ld = [&](int tt) -> float {
        int tq = (tt <= TT - 1) ? tt : (TT - 1);
        return __ldg(gb + (size_t)tq * SSTRIDE);
    };

    auto dots = [&](float pe) {
        const ull* u2 = (const ull*)(ubuf[p]) + half * 12;
        ull a0 = 0, a1 = 0, a2 = 0, a3 = 0;
#pragma unroll
        for (int i = 0; i < 3; i++) {
            ull x0 = u2[4 * i];
            ull x1 = u2[4 * i + 1];
            ull x2 = u2[4 * i + 2];
            ull x3 = u2[4 * i + 3];
            a0 = fma2(EH[4 * i],     x0, a0);
            a1 = fma2(EH[4 * i + 1], x1, a1);
            a2 = fma2(EH[4 * i + 2], x2, a2);
            a3 = fma2(EH[4 * i + 3], x3, a3);
        }
        a0 = add2(a0, a2); a1 = add2(a1, a3); a0 = add2(a0, a1);
        float x, y; unpack2(a0, x, y);
        float dh = x + y;
        float d = dh + __shfl_xor_sync(0xffffffffu, dh, 1);
        val = d * pe;
    };

    auto commit = [&]() {
        if (half == 0 && realg) ubuf[p ^ 1][row] = val;
        p ^= 1;
        __syncthreads();
    };

    auto renorm = [&]() {
        float m = val;
#pragma unroll
        for (int off = 16; off >= 1; off >>= 1)
            m = fmaxf(m, __shfl_xor_sync(0xffffffffu, m, off));
        if (lane == 0) wpart[warp] = m;
        __syncthreads();
        float mm = fmaxf(fmaxf(wpart[0], wpart[1]),
                         fmaxf(wpart[2], fmaxf(wpart[3], 1e-30f)));
        val *= __fdividef(1.f, mm);
        c += __logf(mm);
    };

    float e[8];
#pragma unroll
    for (int i = 0; i < 8; i++) e[i] = ld(1 + i);

    // ---- fast main loop: flag word gates prefetch of t in [t+8, t+15] ----
    const float* gp = gb + (size_t)9 * SSTRIDE;
    volatile ull* fword = (volatile ull*)g_flag8;
    int widx = 2;                         // bytes 16..23 = t 9..16
    ull fv = fword[widx];
    while (t + 16 <= lenm1) {
        while (fv != ONES8) fv = fword[widx];
        __threadfence();                  // acquire: order data loads after flag
        float en[8];
#pragma unroll
        for (int i = 0; i < 8; i++) en[i] = __ldg(gp + (size_t)i * SSTRIDE);
        gp += (size_t)8 * SSTRIDE;
        widx++;
        fv = fword[widx];                 // preload next group's word
#pragma unroll
        for (int i = 0; i < 8; i++) {
            dots(e[i]);
            if (i == 7) renorm();
            commit();
        }
#pragma unroll
        for (int i = 0; i < 8; i++) e[i] = en[i];
        t += 8;
    }

    // ---- slow group: byte-spin only for real t indices ----
    while (t + 8 <= lenm1) {
#pragma unroll
        for (int i = 0; i < 8; i++) {
            int idx = t + 8 + i;
            if (idx <= TT - 1) { while (fb[idx + 7] == 0) {} }
        }
        __threadfence();
#pragma unroll
        for (int i = 0; i < 8; i++) {
            float pe = e[i];
            e[i] = ld(t + 8 + i);
            dots(pe);
            if (i == 7) renorm();
            commit();
        }
        t += 8;
    }

    // ---- tail: r plain steps, then the final step ----
    const int r = lenm1 - t;
    float fe = e[0];
#pragma unroll
    for (int i = 0; i < 8; i++) if (i == r) fe = e[i];

#pragma unroll
    for (int i = 0; i < 7; i++) {
        if (i < r) { dots(e[i]); commit(); }
    }

    {
        dots(fe);
        float s = val * Eend;
#pragma unroll
        for (int off = 16; off >= 1; off >>= 1)
            s += __shfl_xor_sync(0xffffffffu, s, off);
        if (lane == 0) wpart[warp] = s;
        __syncthreads();
        if (g == 0) {
            g_res[bidx] = c + __logf(wpart[0] + wpart[1] + wpart[2] + wpart[3]);
            __threadfence();
            int old = atomicAdd(&g_done, 1);
            s_last = (old == 63);
        }
        __syncthreads();
        if (s_last) {                     // last chain combines + writes out
            __threadfence();
            if (g < BB) out[g] = g_res[g] - g_res[BB + g];
        }
    }
}

extern "C" void kernel_launch(void* const* d_in, const int* in_sizes, int n_in,
                              void* d_out, int out_size) {
    const float* feats = (const float*)d_in[0];
    const void*  tags  = d_in[1];
    const int*   lens  = (const int*)d_in[2];
    const float* W     = (const float*)d_in[3];
    const float* bias  = (const float*)d_in[4];
    const float* beg   = (const float*)d_in[5];
    const float* trans = (const float*)d_in[6];
    const float* endv  = (const float*)d_in[7];
    const void*  bc    = d_in[8];
    const void*  ec    = d_in[9];
    const void*  tc    = d_in[10];

    detect_kernel<<<1, 256>>>((const unsigned int*)tags);
    fused_kernel<<<256, 128>>>((float*)d_out, feats, W, bias, tags,
                               lens, beg, trans, endv, bc, ec, tc);
}

// round 17
// speedup vs baseline: 1.2762x; 1.2762x over previous
#include <cuda_runtime.h>

typedef unsigned long long ull;

#define TT 1024
#define BB 32
#define DD 768
#define LLn 48
#define SSTRIDE (BB * LLn)   // 1536 floats per time step

// Scratch (static device globals — no allocation)
__device__ float g_eem[TT * BB * LLn];   // exp(em + bias), layout [t][b][l]
__device__ float g_eemM[TT * BB * LLn];  // tags ? 0 : eem  (for partial chain)
__device__ float g_res[64];              // [0..31]=fwd, [32..63]=par
__device__ int   g_done;
__device__ int   g_bool_dt;              // 0=uint8, 1=int32, 2=float32

__device__ __forceinline__ ull pack2(float x, float y) {
    ull r; asm("mov.b64 %0, {%1,%2};" : "=l"(r) : "f"(x), "f"(y)); return r;
}
__device__ __forceinline__ void unpack2(ull v, float& x, float& y) {
    asm("mov.b64 {%0,%1}, %2;" : "=f"(x), "=f"(y) : "l"(v));
}
__device__ __forceinline__ ull fma2(ull a, ull b, ull c) {
    ull d; asm("fma.rn.f32x2 %0, %1, %2, %3;" : "=l"(d) : "l"(a), "l"(b), "l"(c)); return d;
}
__device__ __forceinline__ ull add2(ull a, ull b) {
    ull d; asm("add.rn.f32x2 %0, %1, %2;" : "=l"(d) : "l"(a), "l"(b)); return d;
}

__device__ __forceinline__ int loadBool(const void* p, int dt, long idx) {
    if (dt == 1) return ((const int*)p)[idx] != 0;
    if (dt == 0) return ((const unsigned char*)p)[idx] != 0;
    return ((const float*)p)[idx] != 0.f;
}

// ---------------------------------------------------------------------------
// Detect boolean dtype + reset done counter (graph replays!).
// ---------------------------------------------------------------------------
__global__ void detect_kernel(const unsigned int* __restrict__ w) {
    int i = threadIdx.x;
    if (i == 0) g_done = 0;
    int f = 0, u = 0;
#pragma unroll
    for (int q = 0; q < 4; q++) {
        unsigned int v = w[i + q * 256];
        if (v == 0x3F800000u) f = 1;
        else if (v & 0xFFFFFF00u) u = 1;
    }
    int anyf = __syncthreads_or(f);
    int anyu = __syncthreads_or(u);
    if (i == 0) g_bool_dt = anyf ? 2 : (anyu ? 0 : 1);
}

// ---------------------------------------------------------------------------
// Emissions GEMM + exp + tag-mask: writes eem and eemM = tags ? 0 : eem.
// CTA = 128 threads = 64 rows x 2 column-halves; grid 512 (high occupancy).
// ---------------------------------------------------------------------------
#define KT 32
__global__ __launch_bounds__(128) void emis_kernel(const float* __restrict__ feats,
                                                   const float* __restrict__ W,
                                                   const float* __restrict__ bias,
                                                   const void* __restrict__ tags) {
    __shared__ __align__(16) float2 As[64 * 17];   // 64 rows x (16 f2 + pad)
    __shared__ __align__(16) float  Ws[KT * LLn];  // 32 x 48
    const int tid = threadIdx.x;
    const int r = tid >> 1;          // row within block (0..63)
    const int h = tid & 1;           // column half
    const int dt = g_bool_dt;
    const int base_row = blockIdx.x * 64;

    ull acc[12];
#pragma unroll
    for (int i = 0; i < 12; i++) acc[i] = 0ull;

    for (int kt = 0; kt < DD / KT; ++kt) {
        __syncthreads();
        {
            const float2* fg = (const float2*)(feats);
#pragma unroll
            for (int q = 0; q < 8; q++) {
                int n = q * 128 + tid;       // 0..1023
                int rr = n >> 4;
                int c2 = n & 15;
                As[rr * 17 + c2] = fg[(size_t)(base_row + rr) * (DD / 2) + kt * (KT / 2) + c2];
            }
        }
        {
            const float4* wg = (const float4*)(W + kt * KT * LLn);
            float4* ws4 = (float4*)Ws;
#pragma unroll
            for (int q = 0; q < 3; q++) ws4[tid + 128 * q] = wg[tid + 128 * q];
        }
        __syncthreads();

        const float2* arow = As + r * 17;
#pragma unroll
        for (int k2 = 0; k2 < 16; k2++) {
            float2 a2 = arow[k2];
            ull d0 = pack2(a2.x, a2.x);
            ull d1 = pack2(a2.y, a2.y);
            const ulonglong2* w0 = (const ulonglong2*)(Ws + (2 * k2) * LLn + h * 24);
            const ulonglong2* w1 = (const ulonglong2*)(Ws + (2 * k2 + 1) * LLn + h * 24);
#pragma unroll
            for (int j = 0; j < 6; j++) {
                ulonglong2 wa = w0[j];
                ulonglong2 wb = w1[j];
                acc[2 * j]     = fma2(d0, wa.x, acc[2 * j]);
                acc[2 * j + 1] = fma2(d0, wa.y, acc[2 * j + 1]);
                acc[2 * j]     = fma2(d1, wb.x, acc[2 * j]);
                acc[2 * j + 1] = fma2(d1, wb.y, acc[2 * j + 1]);
            }
        }
    }
    // Epilogue: bias + exp; write eem and tag-masked eemM.
    const int grow = base_row + r;       // = t*32 + b
    const long ebase = (long)grow * LLn + h * 24;
    float* orow  = g_eem  + ebase;
    float* orowM = g_eemM + ebase;
#pragma unroll
    for (int jp = 0; jp < 12; jp++) {
        float x, y; unpack2(acc[jp], x, y);
        float2 o;
        o.x = __expf(x + bias[h * 24 + 2 * jp]);
        o.y = __expf(y + bias[h * 24 + 2 * jp + 1]);
        ((float2*)orow)[jp] = o;
        float2 om = o;
        if (loadBool(tags, dt, ebase + 2 * jp))     om.x = 0.f;
        if (loadBool(tags, dt, ebase + 2 * jp + 1)) om.y = 0.f;
        ((float2*)orowM)[jp] = om;
    }
}

// ---------------------------------------------------------------------------
// CRF forward scan: 3 warps per chain (96 threads), one chain per CTA.
// grid 64: bidx<32 fwd(b), else par(b). Lane g: row = g>>1, k-half = g&1.
// Last-finishing chain performs the combine and writes out (done counter).
// ---------------------------------------------------------------------------
__global__ __launch_bounds__(96) void scan_kernel(float* __restrict__ out,
                                                  const int* __restrict__ lens,
                                                  const float* __restrict__ beg,
                                                  const float* __restrict__ trans,
                                                  const float* __restrict__ endv,
                                                  const void* __restrict__ bc,
                                                  const void* __restrict__ ec,
                                                  const void* __restrict__ tc) {
    __shared__ __align__(16) float ubuf[2][LLn];
    __shared__ float wpart[3];
    __shared__ int s_last;
    const int g = threadIdx.x;           // 0..95
    const int warp = g >> 5;
    const int lane = g & 31;
    const int row = g >> 1;              // 0..47
    const int half = g & 1;              // k-half: [24*half, 24*half+24)
    const int bidx = blockIdx.x;
    const int b = bidx & 31;
    const bool is_par = bidx >= 32;
    const int lenm1 = lens[b] - 1;
    const int dt = g_bool_dt;
    const float* gb = (is_par ? g_eemM : g_eem) + b * LLn + row;

    ull EH[12];
#pragma unroll
    for (int j = 0; j < 12; j++) {
        int k = half * 24 + 2 * j;
        float e0 = __expf(trans[row * LLn + k]);
        float e1 = __expf(trans[row * LLn + k + 1]);
        if (is_par) {
            if (loadBool(tc, dt, row * LLn + k))     e0 = 0.f;
            if (loadBool(tc, dt, row * LLn + k + 1)) e1 = 0.f;
        }
        EH[j] = pack2(e0, e1);
    }
    float Eend = 0.f;
    if (half == 0) {
        Eend = __expf(endv[row]);
        if (is_par && loadBool(ec, dt, row)) Eend = 0.f;
    }

    // t = 0 init (eemM folds tags; bc applied here)
    if (half == 0) {
        float u0 = __ldg(gb) * __expf(beg[row]);
        if (is_par && loadBool(bc, dt, row)) u0 = 0.f;
        ubuf[0][row] = u0;
    }
    __syncthreads();

    float c = 0.f;
    int p = 0;
    int t = 1;
    float val = 0.f;

    auto ld = [&](int tt) -> float {     // clamped (slow path / init only)
        int tq = (tt <= TT - 1) ? tt : (TT - 1);
        return __ldg(gb + (size_t)tq * SSTRIDE);
    };

    auto dots = [&](float pe) {
        const ull* u2 = (const ull*)(ubuf[p]) + half * 12;  // 12 pairs
        ull a0 = 0, a1 = 0, a2 = 0, a3 = 0;
#pragma unroll
        for (int i = 0; i < 3; i++) {
            ull x0 = u2[4 * i];
            ull x1 = u2[4 * i + 1];
            ull x2 = u2[4 * i + 2];
            ull x3 = u2[4 * i + 3];
            a0 = fma2(EH[4 * i],     x0, a0);
            a1 = fma2(EH[4 * i + 1], x1, a1);
            a2 = fma2(EH[4 * i + 2], x2, a2);
            a3 = fma2(EH[4 * i + 3], x3, a3);
        }
        a0 = add2(a0, a2); a1 = add2(a1, a3); a0 = add2(a0, a1);
        float x, y; unpack2(a0, x, y);
        float dh = x + y;
        float d = dh + __shfl_xor_sync(0xffffffffu, dh, 1);
        val = d * pe;
    };

    auto commit = [&]() {
        if (half == 0) ubuf[p ^ 1][row] = val;
        p ^= 1;
        __syncthreads();
    };

    auto renorm = [&]() {
        float m = val;
#pragma unroll
        for (int off = 16; off >= 1; off >>= 1)
            m = fmaxf(m, __shfl_xor_sync(0xffffffffu, m, off));
        if (lane == 0) wpart[warp] = m;
        __syncthreads();
        float mm = fmaxf(fmaxf(wpart[0], wpart[1]), fmaxf(wpart[2], 1e-30f));
        val *= __fdividef(1.f, mm);
        c += __logf(mm);
    };

    // 8-slot emission prefetch
    float e[8];
#pragma unroll
    for (int i = 0; i < 8; i++) e[i] = ld(1 + i);

    // ---- fast main loop: unclamped prefetch via advancing pointer ----
    const float* gp = gb + (size_t)9 * SSTRIDE;
    while (t + 16 <= lenm1) {
        float en[8];
#pragma unroll
        for (int i = 0; i < 8; i++) en[i] = __ldg(gp + (size_t)i * SSTRIDE);
        gp += (size_t)8 * SSTRIDE;
#pragma unroll
        for (int i = 0; i < 8; i++) {
            dots(e[i]);
            if (i == 7) renorm();
            commit();
        }
#pragma unroll
        for (int i = 0; i < 8; i++) e[i] = en[i];
        t += 8;
    }

    // ---- slow group: clamped prefetch (at most one group of 8) ----
    while (t + 8 <= lenm1) {
#pragma unroll
        for (int i = 0; i < 8; i++) {
            float pe = e[i];
            e[i] = ld(t + 8 + i);
            dots(pe);
            if (i == 7) renorm();
            commit();
        }
        t += 8;
    }

    // ---- tail: r plain steps (r in [0,7]), then the final step ----
    const int r = lenm1 - t;
    float fe = e[0];
#pragma unroll
    for (int i = 0; i < 8; i++) if (i == r) fe = e[i];

#pragma unroll
    for (int i = 0; i < 7; i++) {
        if (i < r) { dots(e[i]); commit(); }
    }

    // final step + combine by the last-finishing chain
    {
        dots(fe);
        float s = val * Eend;            // Eend==0 on half=1 lanes
#pragma unroll
        for (int off = 16; off >= 1; off >>= 1)
            s += __shfl_xor_sync(0xffffffffu, s, off);
        if (lane == 0) wpart[warp] = s;
        __syncthreads();
        if (g == 0) {
            g_res[bidx] = c + __logf(wpart[0] + wpart[1] + wpart[2]);
            __threadfence();
            int old = atomicAdd(&g_done, 1);
            s_last = (old == 63);
        }
        __syncthreads();
        if (s_last) {
            __threadfence();
            if (g < BB) out[g] = g_res[g] - g_res[BB + g];
        }
    }
}

extern "C" void kernel_launch(void* const* d_in, const int* in_sizes, int n_in,
                              void* d_out, int out_size) {
    const float* feats = (const float*)d_in[0];
    const void*  tags  = d_in[1];
    const int*   lens  = (const int*)d_in[2];
    const float* W     = (const float*)d_in[3];
    const float* bias  = (const float*)d_in[4];
    const float* beg   = (const float*)d_in[5];
    const float* trans = (const float*)d_in[6];
    const float* endv  = (const float*)d_in[7];
    const void*  bc    = d_in[8];
    const void*  ec    = d_in[9];
    const void*  tc    = d_in[10];

    detect_kernel<<<1, 256>>>((const unsigned int*)tags);
    emis_kernel<<<512, 128>>>(feats, W, bias, tags);
    scan_kernel<<<64, 96>>>((float*)d_out, lens, beg, trans, endv, bc, ec, tc);
}